// round 9
// baseline (speedup 1.0000x reference)
#include <cuda_runtime.h>
#include <cstdint>

#define N_ROWS  262144
#define DIM     256
#define CLUSTER 512
#define SLACK   1024
#define NPAIRS  (CLUSTER * (CLUSTER - 1) / 2)   // 130816
#define NTILES  136                             // 16*17/2 upper-tri 32x32 tiles
#define SCTAS   256
#define ROWS_PER_SCTA (N_ROWS / SCTAS)          // 1024
#define CPAD    32                              // 1 cursor per 128B line

// ---- device scratch (zero-initialized at module load; the LAST k_pdist CTA
//      resets everything it dirtied so each graph replay sees zeros) ----
__device__ int   d_cursor[CLUSTER * CPAD];         // padded: 1 line per counter
__device__ int   d_perm[CLUSTER * SLACK];          // 2 MB
__device__ float d_centers[CLUSTER * DIM];         // 512 KB (L2-resident)
__device__ float d_norms[CLUSTER];
__device__ float d_pair_sum;
__device__ int   d_done;

__device__ __forceinline__ float4 ldcs4(const float* p) {
    float4 v;
    asm volatile("ld.global.cs.v4.f32 {%0,%1,%2,%3}, [%4];"
                 : "=f"(v.x), "=f"(v.y), "=f"(v.z), "=f"(v.w) : "l"(p));
    return v;
}

// ---------------------------------------------------------------------------
// k_scatter: CTA-aggregated counting scatter. Reservation atomics hit 512
// DISTINCT 128B lines (padded counters) -> ~192 LTS slices active instead of
// 16 -> reservation phase ~1.5k cyc instead of ~16k.
// ---------------------------------------------------------------------------
__global__ void __launch_bounds__(512) k_scatter(const int* __restrict__ label) {
    __shared__ int hist[CLUSTER];
    __shared__ int curs[CLUSTER];
    int t  = threadIdx.x;
    int r0 = blockIdx.x * ROWS_PER_SCTA;

    hist[t] = 0;
    __syncthreads();

    int l0 = label[r0 + t];
    int l1 = label[r0 + 512 + t];
    atomicAdd(&hist[l0], 1);
    atomicAdd(&hist[l1], 1);
    __syncthreads();

    int h = hist[t];
    curs[t] = t * SLACK + ((h > 0) ? atomicAdd(&d_cursor[t * CPAD], h) : 0);
    __syncthreads();

    int p0 = atomicAdd(&curs[l0], 1);
    d_perm[p0] = r0 + t;
    int p1 = atomicAdd(&curs[l1], 1);
    d_perm[p1] = r0 + 512 + t;
}

// ---------------------------------------------------------------------------
// k_sums: 2 CTAs per cluster (128-column halves), 256 threads. 8 independent
// LDG.128 in flight per thread. Measured ~6.9 TB/s: roofline-bound, frozen.
// ---------------------------------------------------------------------------
__global__ void __launch_bounds__(256) k_sums(const float* __restrict__ matrix) {
    int bx = blockIdx.x;
    int c  = bx >> 1;
    int hc = bx & 1;
    int t  = threadIdx.x;
    int cg = t & 31;
    int s  = t >> 5;
    int colbase = hc * 128 + cg * 4;

    int cnt = d_cursor[c * CPAD];
    const int* __restrict__ p = d_perm + c * SLACK;

    __shared__ int    sidx[256];
    __shared__ float4 part[256];

    float4 acc = make_float4(0.f, 0.f, 0.f, 0.f);

    int base = 0;
    for (; base + 256 <= cnt; base += 256) {
        __syncthreads();
        sidx[t] = p[base + t];
        __syncthreads();
        for (int r = 0; r < 32; r += 8) {
            float4 v[8];
#pragma unroll
            for (int u = 0; u < 8; u++) {
                int row = sidx[(r + u) * 8 + s];
                v[u] = ldcs4(&matrix[(size_t)row * DIM + colbase]);
            }
            float4 s01, s23, s45, s67, sA, sB;
            s01.x = v[0].x + v[1].x; s01.y = v[0].y + v[1].y; s01.z = v[0].z + v[1].z; s01.w = v[0].w + v[1].w;
            s23.x = v[2].x + v[3].x; s23.y = v[2].y + v[3].y; s23.z = v[2].z + v[3].z; s23.w = v[2].w + v[3].w;
            s45.x = v[4].x + v[5].x; s45.y = v[4].y + v[5].y; s45.z = v[4].z + v[5].z; s45.w = v[4].w + v[5].w;
            s67.x = v[6].x + v[7].x; s67.y = v[6].y + v[7].y; s67.z = v[6].z + v[7].z; s67.w = v[6].w + v[7].w;
            sA.x = s01.x + s23.x; sA.y = s01.y + s23.y; sA.z = s01.z + s23.z; sA.w = s01.w + s23.w;
            sB.x = s45.x + s67.x; sB.y = s45.y + s67.y; sB.z = s45.z + s67.z; sB.w = s45.w + s67.w;
            acc.x += sA.x + sB.x; acc.y += sA.y + sB.y;
            acc.z += sA.z + sB.z; acc.w += sA.w + sB.w;
        }
    }
    {   // tail
        int m = cnt - base;
        __syncthreads();
        if (t < m) sidx[t] = p[base + t];
        __syncthreads();
        for (int r = s; r < m; r += 8) {
            int row = sidx[r];
            float4 v = ldcs4(&matrix[(size_t)row * DIM + colbase]);
            acc.x += v.x; acc.y += v.y; acc.z += v.z; acc.w += v.w;
        }
    }

    part[t] = acc;
    __syncthreads();

    if (t < 32) {
        float4 cen = make_float4(0.f, 0.f, 0.f, 0.f);
#pragma unroll
        for (int k = 0; k < 8; k++) {
            float4 a = part[t + k * 32];
            cen.x += a.x; cen.y += a.y; cen.z += a.z; cen.w += a.w;
        }
        float inv = 1.0f / fmaxf((float)cnt, 1.0f);
        cen.x *= inv; cen.y *= inv; cen.z *= inv; cen.w *= inv;
        *(float4*)&d_centers[c * DIM + hc * 128 + t * 4] = cen;

        float nrm = cen.x * cen.x + cen.y * cen.y + cen.z * cen.z + cen.w * cen.w;
#pragma unroll
        for (int o = 16; o > 0; o >>= 1)
            nrm += __shfl_down_sync(0xFFFFFFFFu, nrm, o);
        if (t == 0) atomicAdd(&d_norms[c], nrm);
    }
}

// ---------------------------------------------------------------------------
// k_pdist: 136 upper-tri 32x32 tiles, 512 threads (16 warps).
// 8x8 micro-tile: 64 FFMA per 4 LDS.128 (FMA:LDS = 16:1). Warp w = d-slice;
// lane = dh*16+pos (dh = d parity, pos = 4x4 (pi,pj)). Epilogue: shfl-16
// dh-fold, 4-round smem tree, sqrt spread over all threads. Last CTA writes
// the output and resets all device state for the next graph replay.
// ---------------------------------------------------------------------------
#define TPAD 36
__global__ void __launch_bounds__(512) k_pdist(float* __restrict__ out) {
    // decode upper-tri tile index -> (bi, bj), bi <= bj
    int n = blockIdx.x;
    int bi = 0;
    while (n >= 16 - bi) { n -= 16 - bi; bi++; }
    int bj = bi + n;

    __shared__ __align__(16) float S[2 * 128 * TPAD];   // 9216 floats
    float (*At)[TPAD] = (float (*)[TPAD])S;
    float (*Bt)[TPAD] = (float (*)[TPAD])(S + 128 * TPAD);
    float4* red4 = (float4*)S;
    float*  dots = S + 128 * TPAD;     // overlays Bt (dead by then)
    __shared__ float partw[16];
    __shared__ int   islast;

    int t    = threadIdx.x;
    int w    = t >> 5;        // warp = d-slice 0..15
    int lane = t & 31;
    int dh   = lane >> 4;     // d parity
    int pos  = lane & 15;
    int pi   = pos >> 2;      // i block: rows pi*8..pi*8+7
    int pj   = pos & 3;       // j block: rows pj*8..pj*8+7

    // loader mapping (proven round-6 pattern)
    int half = t >> 8;        // 0 -> A, 1 -> B
    int iblk = (t >> 5) & 7;
    int dlo  = t & 31;

    float acc[8][8];
#pragma unroll
    for (int r = 0; r < 8; r++)
#pragma unroll
        for (int c = 0; c < 8; c++) acc[r][c] = 0.0f;

    for (int ck = 0; ck < DIM; ck += 128) {
        __syncthreads();
        {
            int bX = half ? bj : bi;
            float (*T)[TPAD] = half ? Bt : At;
            const float* src = &d_centers[(bX * 32 + iblk * 4) * DIM + ck];
#pragma unroll
            for (int k = 0; k < 4; k++) {
                int dd = dlo + k * 32;
                float4 v;
                v.x = src[0 * DIM + dd];
                v.y = src[1 * DIM + dd];
                v.z = src[2 * DIM + dd];
                v.w = src[3 * DIM + dd];
                *(float4*)&T[dd][iblk * 4] = v;
            }
        }
        __syncthreads();

#pragma unroll
        for (int k = 0; k < 4; k++) {
            int dl = w * 8 + dh + 2 * k;
            float4 a0 = *(float4*)&At[dl][pi * 8];
            float4 a1 = *(float4*)&At[dl][pi * 8 + 4];
            float4 b0 = *(float4*)&Bt[dl][pj * 8];
            float4 b1 = *(float4*)&Bt[dl][pj * 8 + 4];
            float av[8] = {a0.x, a0.y, a0.z, a0.w, a1.x, a1.y, a1.z, a1.w};
            float bv[8] = {b0.x, b0.y, b0.z, b0.w, b1.x, b1.y, b1.z, b1.w};
#pragma unroll
            for (int r = 0; r < 8; r++)
#pragma unroll
                for (int c = 0; c < 8; c++)
                    acc[r][c] += av[r] * bv[c];
        }
    }

    // fold dh=1 into dh=0 lanes
#pragma unroll
    for (int r = 0; r < 8; r++)
#pragma unroll
        for (int c = 0; c < 8; c++)
            acc[r][c] += __shfl_down_sync(0xFFFFFFFFu, acc[r][c], 16);

    bool lower = (lane < 16);

    // 4-round smem tree over warps: 16 -> 8 -> 4 -> 2 -> 1
#pragma unroll
    for (int span = 8; span >= 1; span >>= 1) {
        __syncthreads();
        if (w >= span && w < 2 * span && lower) {
            int slot = w - span;
#pragma unroll
            for (int r = 0; r < 8; r++)
#pragma unroll
                for (int cq = 0; cq < 2; cq++) {
                    float4 v = make_float4(acc[r][cq*4], acc[r][cq*4+1],
                                           acc[r][cq*4+2], acc[r][cq*4+3]);
                    red4[((slot * 16 + pos) * 17) + r * 2 + cq] = v;
                }
        }
        __syncthreads();
        if (w < span && lower) {
#pragma unroll
            for (int r = 0; r < 8; r++)
#pragma unroll
                for (int cq = 0; cq < 2; cq++) {
                    float4 v = red4[((w * 16 + pos) * 17) + r * 2 + cq];
                    acc[r][cq*4]   += v.x; acc[r][cq*4+1] += v.y;
                    acc[r][cq*4+2] += v.z; acc[r][cq*4+3] += v.w;
                }
        }
    }

    // warp 0 lanes 0..15 hold full dots; scatter to dots[i2*32+j2]
    __syncthreads();
    if (w == 0 && lower) {
#pragma unroll
        for (int r = 0; r < 8; r++)
#pragma unroll
            for (int cq = 0; cq < 2; cq++)
                *(float4*)&dots[(pi * 8 + r) * 32 + pj * 8 + cq * 4] =
                    make_float4(acc[r][cq*4], acc[r][cq*4+1],
                                acc[r][cq*4+2], acc[r][cq*4+3]);
    }
    __syncthreads();

    // each thread: 2 pairs -> sqrt -> sum
    float local = 0.0f;
#pragma unroll
    for (int q = 0; q < 2; q++) {
        int p  = t * 2 + q;
        int i2 = p >> 5;
        int j2 = p & 31;
        int gi = bi * 32 + i2;
        int gj = bj * 32 + j2;
        if (gi < gj) {
            float sq = d_norms[gi] + d_norms[gj] - 2.0f * dots[p];
            local += sqrtf(fmaxf(sq, 1e-12f));
        }
    }

#pragma unroll
    for (int o = 16; o > 0; o >>= 1)
        local += __shfl_down_sync(0xFFFFFFFFu, local, o);
    if (lane == 0) partw[w] = local;
    __syncthreads();
    if (t == 0) {
        float sum = 0.0f;
#pragma unroll
        for (int i = 0; i < 16; i++) sum += partw[i];
        atomicAdd(&d_pair_sum, sum);
        __threadfence();
        islast = (atomicAdd(&d_done, 1) == NTILES - 1) ? 1 : 0;
    }
    __syncthreads();

    // last CTA: emit output, then reset all device state for the next replay
    if (islast) {
        if (t == 0) {
            __threadfence();
            out[0] = -(*(volatile float*)&d_pair_sum) / (float)NPAIRS;
            d_pair_sum = 0.0f;
            d_done = 0;
        }
        d_cursor[t * CPAD] = 0;
        d_norms[t]         = 0.0f;
    }
}

// ---------------------------------------------------------------------------
extern "C" void kernel_launch(void* const* d_in, const int* in_sizes, int n_in,
                              void* d_out, int out_size) {
    const float* matrix = (const float*)d_in[0];
    const int*   label  = (const int*)d_in[1];
    float*       out    = (float*)d_out;

    k_scatter<<<SCTAS, 512>>>(label);
    k_sums<<<CLUSTER * 2, 256>>>(matrix);
    k_pdist<<<NTILES, 512>>>(out);
}

// round 10
// speedup vs baseline: 1.0937x; 1.0937x over previous
#include <cuda_runtime.h>
#include <cstdint>

#define N_ROWS  262144
#define DIM     256
#define CLUSTER 512
#define SLACK   1024
#define NPAIRS  (CLUSTER * (CLUSTER - 1) / 2)   // 130816
#define NTILES  136                             // 16*17/2 upper-tri 32x32 tiles
#define SCTAS   128
#define ROWS_PER_SCTA (N_ROWS / SCTAS)          // 2048
#define CPAD    32                              // 1 cursor per 128B line

// ---- device scratch (zero-initialized at module load; the LAST k_pdist CTA
//      resets everything it dirtied so each graph replay sees zeros) ----
__device__ int   d_cursor[CLUSTER * CPAD];         // padded: 1 line per counter
__device__ int   d_perm[CLUSTER * SLACK];          // 2 MB
__device__ float d_centers[CLUSTER * DIM];         // 512 KB (L2-resident)
__device__ float d_norms[CLUSTER];
__device__ float d_pair_sum;
__device__ int   d_done;

__device__ __forceinline__ float4 ldcs4(const float* p) {
    float4 v;
    asm volatile("ld.global.cs.v4.f32 {%0,%1,%2,%3}, [%4];"
                 : "=f"(v.x), "=f"(v.y), "=f"(v.z), "=f"(v.w) : "l"(p));
    return v;
}

// ---------------------------------------------------------------------------
// k_scatter: CTA-aggregated counting scatter, 128 CTAs x 2048 rows
// (measured-best CTA count). Reservation atomics hit padded 128B lines.
// ---------------------------------------------------------------------------
__global__ void __launch_bounds__(512) k_scatter(const int* __restrict__ label) {
    __shared__ int hist[CLUSTER];
    __shared__ int curs[CLUSTER];
    int t  = threadIdx.x;
    int r0 = blockIdx.x * ROWS_PER_SCTA;

    hist[t] = 0;
    __syncthreads();

    int labs[4];
#pragma unroll
    for (int k = 0; k < 4; k++) {
        labs[k] = label[r0 + k * 512 + t];
        atomicAdd(&hist[labs[k]], 1);
    }
    __syncthreads();

    int h = hist[t];
    curs[t] = t * SLACK + ((h > 0) ? atomicAdd(&d_cursor[t * CPAD], h) : 0);
    __syncthreads();

#pragma unroll
    for (int k = 0; k < 4; k++) {
        int pos = atomicAdd(&curs[labs[k]], 1);
        d_perm[pos] = r0 + k * 512 + t;
    }
}

// ---------------------------------------------------------------------------
// k_sums: 2 CTAs per cluster (128-column halves), 256 threads. 8 independent
// LDG.128 in flight per thread. Measured ~6.9 TB/s: roofline-bound, frozen.
// ---------------------------------------------------------------------------
__global__ void __launch_bounds__(256) k_sums(const float* __restrict__ matrix) {
    int bx = blockIdx.x;
    int c  = bx >> 1;
    int hc = bx & 1;
    int t  = threadIdx.x;
    int cg = t & 31;
    int s  = t >> 5;
    int colbase = hc * 128 + cg * 4;

    int cnt = d_cursor[c * CPAD];
    const int* __restrict__ p = d_perm + c * SLACK;

    __shared__ int    sidx[256];
    __shared__ float4 part[256];

    float4 acc = make_float4(0.f, 0.f, 0.f, 0.f);

    int base = 0;
    for (; base + 256 <= cnt; base += 256) {
        __syncthreads();
        sidx[t] = p[base + t];
        __syncthreads();
        for (int r = 0; r < 32; r += 8) {
            float4 v[8];
#pragma unroll
            for (int u = 0; u < 8; u++) {
                int row = sidx[(r + u) * 8 + s];
                v[u] = ldcs4(&matrix[(size_t)row * DIM + colbase]);
            }
            float4 s01, s23, s45, s67, sA, sB;
            s01.x = v[0].x + v[1].x; s01.y = v[0].y + v[1].y; s01.z = v[0].z + v[1].z; s01.w = v[0].w + v[1].w;
            s23.x = v[2].x + v[3].x; s23.y = v[2].y + v[3].y; s23.z = v[2].z + v[3].z; s23.w = v[2].w + v[3].w;
            s45.x = v[4].x + v[5].x; s45.y = v[4].y + v[5].y; s45.z = v[4].z + v[5].z; s45.w = v[4].w + v[5].w;
            s67.x = v[6].x + v[7].x; s67.y = v[6].y + v[7].y; s67.z = v[6].z + v[7].z; s67.w = v[6].w + v[7].w;
            sA.x = s01.x + s23.x; sA.y = s01.y + s23.y; sA.z = s01.z + s23.z; sA.w = s01.w + s23.w;
            sB.x = s45.x + s67.x; sB.y = s45.y + s67.y; sB.z = s45.z + s67.z; sB.w = s45.w + s67.w;
            acc.x += sA.x + sB.x; acc.y += sA.y + sB.y;
            acc.z += sA.z + sB.z; acc.w += sA.w + sB.w;
        }
    }
    {   // tail
        int m = cnt - base;
        __syncthreads();
        if (t < m) sidx[t] = p[base + t];
        __syncthreads();
        for (int r = s; r < m; r += 8) {
            int row = sidx[r];
            float4 v = ldcs4(&matrix[(size_t)row * DIM + colbase]);
            acc.x += v.x; acc.y += v.y; acc.z += v.z; acc.w += v.w;
        }
    }

    part[t] = acc;
    __syncthreads();

    if (t < 32) {
        float4 cen = make_float4(0.f, 0.f, 0.f, 0.f);
#pragma unroll
        for (int k = 0; k < 8; k++) {
            float4 a = part[t + k * 32];
            cen.x += a.x; cen.y += a.y; cen.z += a.z; cen.w += a.w;
        }
        float inv = 1.0f / fmaxf((float)cnt, 1.0f);
        cen.x *= inv; cen.y *= inv; cen.z *= inv; cen.w *= inv;
        *(float4*)&d_centers[c * DIM + hc * 128 + t * 4] = cen;

        float nrm = cen.x * cen.x + cen.y * cen.y + cen.z * cen.z + cen.w * cen.w;
#pragma unroll
        for (int o = 16; o > 0; o >>= 1)
            nrm += __shfl_down_sync(0xFFFFFFFFu, nrm, o);
        if (t == 0) atomicAdd(&d_norms[c], nrm);
    }
}

// ---------------------------------------------------------------------------
// k_pdist: 136 upper-tri 32x32 tiles, 512 threads (16 warps).
// 8x8 micro-tile: 64 FFMA per 4 LDS.128 (FMA:LDS = 16:1). Warp w = d-slice;
// lane = dh*16+pos (dh = d parity, pos = 4x4 (pi,pj)). Epilogue: shfl-16
// dh-fold, 4-round smem tree, sqrt spread over all threads. Last CTA writes
// the output and resets all device state for the next graph replay.
// ---------------------------------------------------------------------------
#define TPAD 36
__global__ void __launch_bounds__(512) k_pdist(float* __restrict__ out) {
    // decode upper-tri tile index -> (bi, bj), bi <= bj
    int n = blockIdx.x;
    int bi = 0;
    while (n >= 16 - bi) { n -= 16 - bi; bi++; }
    int bj = bi + n;

    __shared__ __align__(16) float S[2 * 128 * TPAD];   // 9216 floats
    float (*At)[TPAD] = (float (*)[TPAD])S;
    float (*Bt)[TPAD] = (float (*)[TPAD])(S + 128 * TPAD);
    float4* red4 = (float4*)S;
    float*  dots = S + 128 * TPAD;     // overlays Bt (dead by then)
    __shared__ float partw[16];
    __shared__ int   islast;

    int t    = threadIdx.x;
    int w    = t >> 5;        // warp = d-slice 0..15
    int lane = t & 31;
    int dh   = lane >> 4;     // d parity
    int pos  = lane & 15;
    int pi   = pos >> 2;      // i block: rows pi*8..pi*8+7
    int pj   = pos & 3;       // j block: rows pj*8..pj*8+7

    // loader mapping (proven round-6 pattern)
    int half = t >> 8;        // 0 -> A, 1 -> B
    int iblk = (t >> 5) & 7;
    int dlo  = t & 31;

    float acc[8][8];
#pragma unroll
    for (int r = 0; r < 8; r++)
#pragma unroll
        for (int c = 0; c < 8; c++) acc[r][c] = 0.0f;

    for (int ck = 0; ck < DIM; ck += 128) {
        __syncthreads();
        {
            int bX = half ? bj : bi;
            float (*T)[TPAD] = half ? Bt : At;
            const float* src = &d_centers[(bX * 32 + iblk * 4) * DIM + ck];
#pragma unroll
            for (int k = 0; k < 4; k++) {
                int dd = dlo + k * 32;
                float4 v;
                v.x = src[0 * DIM + dd];
                v.y = src[1 * DIM + dd];
                v.z = src[2 * DIM + dd];
                v.w = src[3 * DIM + dd];
                *(float4*)&T[dd][iblk * 4] = v;
            }
        }
        __syncthreads();

#pragma unroll
        for (int k = 0; k < 4; k++) {
            int dl = w * 8 + dh + 2 * k;
            float4 a0 = *(float4*)&At[dl][pi * 8];
            float4 a1 = *(float4*)&At[dl][pi * 8 + 4];
            float4 b0 = *(float4*)&Bt[dl][pj * 8];
            float4 b1 = *(float4*)&Bt[dl][pj * 8 + 4];
            float av[8] = {a0.x, a0.y, a0.z, a0.w, a1.x, a1.y, a1.z, a1.w};
            float bv[8] = {b0.x, b0.y, b0.z, b0.w, b1.x, b1.y, b1.z, b1.w};
#pragma unroll
            for (int r = 0; r < 8; r++)
#pragma unroll
                for (int c = 0; c < 8; c++)
                    acc[r][c] += av[r] * bv[c];
        }
    }

    // fold dh=1 into dh=0 lanes
#pragma unroll
    for (int r = 0; r < 8; r++)
#pragma unroll
        for (int c = 0; c < 8; c++)
            acc[r][c] += __shfl_down_sync(0xFFFFFFFFu, acc[r][c], 16);

    bool lower = (lane < 16);

    // 4-round smem tree over warps: 16 -> 8 -> 4 -> 2 -> 1
#pragma unroll
    for (int span = 8; span >= 1; span >>= 1) {
        __syncthreads();
        if (w >= span && w < 2 * span && lower) {
            int slot = w - span;
#pragma unroll
            for (int r = 0; r < 8; r++)
#pragma unroll
                for (int cq = 0; cq < 2; cq++) {
                    float4 v = make_float4(acc[r][cq*4], acc[r][cq*4+1],
                                           acc[r][cq*4+2], acc[r][cq*4+3]);
                    red4[((slot * 16 + pos) * 17) + r * 2 + cq] = v;
                }
        }
        __syncthreads();
        if (w < span && lower) {
#pragma unroll
            for (int r = 0; r < 8; r++)
#pragma unroll
                for (int cq = 0; cq < 2; cq++) {
                    float4 v = red4[((w * 16 + pos) * 17) + r * 2 + cq];
                    acc[r][cq*4]   += v.x; acc[r][cq*4+1] += v.y;
                    acc[r][cq*4+2] += v.z; acc[r][cq*4+3] += v.w;
                }
        }
    }

    // warp 0 lanes 0..15 hold full dots; scatter to dots[i2*32+j2]
    __syncthreads();
    if (w == 0 && lower) {
#pragma unroll
        for (int r = 0; r < 8; r++)
#pragma unroll
            for (int cq = 0; cq < 2; cq++)
                *(float4*)&dots[(pi * 8 + r) * 32 + pj * 8 + cq * 4] =
                    make_float4(acc[r][cq*4], acc[r][cq*4+1],
                                acc[r][cq*4+2], acc[r][cq*4+3]);
    }
    __syncthreads();

    // each thread: 2 pairs -> sqrt -> sum
    float local = 0.0f;
#pragma unroll
    for (int q = 0; q < 2; q++) {
        int p  = t * 2 + q;
        int i2 = p >> 5;
        int j2 = p & 31;
        int gi = bi * 32 + i2;
        int gj = bj * 32 + j2;
        if (gi < gj) {
            float sq = d_norms[gi] + d_norms[gj] - 2.0f * dots[p];
            local += sqrtf(fmaxf(sq, 1e-12f));
        }
    }

#pragma unroll
    for (int o = 16; o > 0; o >>= 1)
        local += __shfl_down_sync(0xFFFFFFFFu, local, o);
    if (lane == 0) partw[w] = local;
    __syncthreads();
    if (t == 0) {
        float sum = 0.0f;
#pragma unroll
        for (int i = 0; i < 16; i++) sum += partw[i];
        atomicAdd(&d_pair_sum, sum);
        __threadfence();
        islast = (atomicAdd(&d_done, 1) == NTILES - 1) ? 1 : 0;
    }
    __syncthreads();

    // last CTA: emit output, then reset all device state for the next replay
    if (islast) {
        if (t == 0) {
            __threadfence();
            out[0] = -(*(volatile float*)&d_pair_sum) / (float)NPAIRS;
            d_pair_sum = 0.0f;
            d_done = 0;
        }
        d_cursor[t * CPAD] = 0;
        d_norms[t]         = 0.0f;
    }
}

// ---------------------------------------------------------------------------
extern "C" void kernel_launch(void* const* d_in, const int* in_sizes, int n_in,
                              void* d_out, int out_size) {
    const float* matrix = (const float*)d_in[0];
    const int*   label  = (const int*)d_in[1];
    float*       out    = (float*)d_out;

    k_scatter<<<SCTAS, 512>>>(label);
    k_sums<<<CLUSTER * 2, 256>>>(matrix);
    k_pdist<<<NTILES, 512>>>(out);
}